// round 13
// baseline (speedup 1.0000x reference)
#include <cuda_runtime.h>

#define NB 4
#define NN 3136
#define NTOK (NB*NN)
typedef unsigned long long u64;

__device__ float d_q[NTOK*64];
__device__ float d_k[NTOK*64];
__device__ float d_v[NTOK*64];
__device__ float d_g[NTOK*64];
__device__ float d_x1[NTOK*64];
__device__ float d_xn2[NTOK*64];
__device__ float d_cat[NTOK*512];
__device__ float d_sumv[NB*64];
__device__ float d_svp[NB*32*64];
__device__ float d_Wc[64*192];
__device__ float d_Wb[192];
__device__ float d_lwT[576*64];
__device__ float d_w1t[512*64];
__device__ float d_wd[NTOK*8];
__device__ int   d_wi[NTOK*8];
__device__ float d_bs[NTOK];
__device__ float d_cv[NTOK*56];
__device__ int   d_ci[NTOK*56];

__device__ __forceinline__ u64 ffma2(u64 a, u64 b, u64 c) {
    u64 d; asm("fma.rn.f32x2 %0, %1, %2, %3;" : "=l"(d) : "l"(a), "l"(b), "l"(c)); return d;
}
__device__ __forceinline__ u64 fadd2(u64 a, u64 b) {
    u64 d; asm("add.rn.f32x2 %0, %1, %2;" : "=l"(d) : "l"(a), "l"(b)); return d;
}
__device__ __forceinline__ u64 fmul2(u64 a, u64 b) {
    u64 d; asm("mul.rn.f32x2 %0, %1, %2;" : "=l"(d) : "l"(a), "l"(b)); return d;
}
__device__ __forceinline__ u64 pk2(float v) {
    u64 d; asm("mov.b64 %0, {%1, %1};" : "=l"(d) : "f"(v)); return d;
}
__device__ __forceinline__ u64 pk(float lo, float hi) {
    u64 d; asm("mov.b64 %0, {%1, %2};" : "=l"(d) : "f"(lo), "f"(hi)); return d;
}
__device__ __forceinline__ void upk(u64 v, float& lo, float& hi) {
    asm("mov.b64 {%0, %1}, %2;" : "=f"(lo), "=f"(hi) : "l"(v));
}

__global__ void k0_prep(const float* __restrict__ wq, const float* __restrict__ bq,
                        const float* __restrict__ wkv, const float* __restrict__ bkv,
                        const float* __restrict__ lw, const float* __restrict__ w1)
{
    int i = blockIdx.x * 256 + threadIdx.x;
    if (i < 64*192) {
        int k = i / 192, f = i % 192;
        d_Wc[i] = (f < 64) ? wq[k*64 + f] : wkv[k*128 + (f - 64)];
    }
    int j = i - 64*192;
    if (j >= 0 && j < 192) d_Wb[j] = (j < 64) ? bq[j] : bkv[j - 64];
    int l = i - (64*192 + 192);
    if (l >= 0 && l < 576*64) d_lwT[l] = lw[(l % 64)*576 + (l / 64)];
    int m = i - (64*192 + 192 + 576*64);
    if (m >= 0 && m < 512*64) d_w1t[m] = w1[(m % 64)*512 + (m / 64)];
}

// LN1 + fused QKV projection: 32 tokens/block, f32x2
__global__ __launch_bounds__(256) void k1_lnqkv(const float* __restrict__ x,
                                                const float* __restrict__ n1g,
                                                const float* __restrict__ n1b)
{
    __shared__ float xs[32*65];
    int tid = threadIdx.x;
    int tok0 = blockIdx.x * 32;
    for (int idx = tid; idx < 2048; idx += 256) {
        int t = idx >> 6, c = idx & 63;
        xs[t*65 + c] = x[(tok0 + t)*64 + c];
    }
    __syncthreads();
    int t = tid >> 3, fg = tid & 7;
    float vals[8], s1 = 0.f, s2 = 0.f;
#pragma unroll
    for (int i = 0; i < 8; i++) {
        float v = xs[t*65 + fg*8 + i];
        vals[i] = v; s1 += v; s2 += v*v;
    }
#pragma unroll
    for (int o = 1; o < 8; o <<= 1) {
        s1 += __shfl_xor_sync(0xffffffffu, s1, o);
        s2 += __shfl_xor_sync(0xffffffffu, s2, o);
    }
    float mean = s1 * (1.f/64.f);
    float rs = rsqrtf(s2*(1.f/64.f) - mean*mean + 1e-5f);
#pragma unroll
    for (int i = 0; i < 8; i++) {
        int c = fg*8 + i;
        xs[t*65 + c] = (vals[i] - mean) * rs * n1g[c] + n1b[c];
    }
    __syncthreads();
    int f0 = fg * 24;
    u64 acc[12];
#pragma unroll
    for (int j = 0; j < 12; j++) acc[j] = pk(d_Wb[f0 + 2*j], d_Wb[f0 + 2*j + 1]);
#pragma unroll 4
    for (int k = 0; k < 64; k++) {
        u64 xv2 = pk2(xs[t*65 + k]);
        const ulonglong2* wr = (const ulonglong2*)&d_Wc[k*192 + f0];
#pragma unroll
        for (int j2 = 0; j2 < 6; j2++) {
            ulonglong2 w = wr[j2];
            acc[j2*2+0] = ffma2(xv2, w.x, acc[j2*2+0]);
            acc[j2*2+1] = ffma2(xv2, w.y, acc[j2*2+1]);
        }
    }
    int tok = tok0 + t;
#pragma unroll
    for (int j = 0; j < 12; j++) {
        float lo, hi; upk(acc[j], lo, hi);
        int f = f0 + 2*j;
#pragma unroll
        for (int e = 0; e < 2; e++) {
            int ff = f + e;
            float v = e ? hi : lo;
            if (ff < 64)       d_q[tok*64 + ff] = v;
            else if (ff < 128) d_k[tok*64 + ff - 64] = v;
            else               d_v[tok*64 + ff - 128] = v;
        }
    }
}

__global__ void k2a_sumv()
{
    int b = blockIdx.x, oct = blockIdx.y;
    int c = threadIdx.x & 63, sg = threadIdx.x >> 6;
    float a = 0.f;
    int base = b*NN + oct*392 + sg*98;
#pragma unroll 4
    for (int j = 0; j < 98; j++) a += d_v[(base + j)*64 + c];
    d_svp[(b*32 + oct*4 + sg)*64 + c] = a;
}
__global__ void k2b_sumv()
{
    __shared__ float red[4][64];
    int b = blockIdx.x;
    int c = threadIdx.x & 63, part = threadIdx.x >> 6;
    float a = 0.f;
#pragma unroll
    for (int s = 0; s < 8; s++) a += d_svp[(b*32 + part*8 + s)*64 + c];
    red[part][c] = a;
    __syncthreads();
    if (part == 0)
        d_sumv[b*64 + c] = (red[0][c] + red[1][c]) + (red[2][c] + red[3][c]);
}

#define SWP(a,b,ia,ib) if (a > b) { float tf_=a; a=b; b=tf_; int ti_=ia; ia=ib; ib=ti_; }
#define KSPLIT 7
#define TPS 448
// smem: qs 64*68*4=17408 | kt 2*17408=34816 | ss 2*64*67*4=34304  -> 86528
#define K3A_SMEM 86528

// Warp-specialized scorer: 64 queries x 448 keys per block (7 tiles of 64).
// Threads 0-127: GEMM (4q x 8k register tiles). Threads 128-191: one scan
// thread per query — prefetch next k-tile (cp.async) + top-8 scan of the
// PREVIOUS tile's scores (double-buffered ss). One barrier per tile.
__global__ __launch_bounds__(192, 2) void k3a_score()
{
    extern __shared__ __align__(16) char smem[];
    float* qs  = (float*)smem;                 // 64*68
    float* ktb = (float*)(smem + 17408);       // 2 * 64*68
    float* ssb = (float*)(smem + 52224);       // 2 * 64*67
    int tid = threadIdx.x;
    int b = blockIdx.z, split = blockIdx.y;
    int q0 = blockIdx.x * 64;
    int kbase = split * TPS;
    bool isScan = (tid >= 128);
    int st = tid - 128;                        // scan thread id 0..63

    if (!isScan) {
        int r0 = tid >> 4, c4 = tid & 15;
#pragma unroll
        for (int i = 0; i < 8; i++) {
            int row = i*8 + r0;
            *(float4*)&qs[row*68 + c4*4] =
                *(const float4*)&d_q[(b*NN + q0 + row)*64 + c4*4];
        }
    } else {
        // prefetch tile 0 into buffer 0
        const float* kb0 = &d_k[(b*NN + kbase)*64];
#pragma unroll
        for (int i = 0; i < 16; i++) {
            int fi = i*64 + st;
            int row = fi >> 4, cc = fi & 15;
            unsigned int dst = (unsigned int)__cvta_generic_to_shared(&ktb[row*68 + cc*4]);
            asm volatile("cp.async.cg.shared.global [%0], [%1], 16;"
                         :: "r"(dst), "l"(kb0 + row*64 + cc*4));
        }
        asm volatile("cp.async.commit_group;");
        asm volatile("cp.async.wait_group 0;");
    }

    int qg = tid >> 3, kg = tid & 7;           // GEMM identity (tid<128)
    float t0=-1e30f,t1=-1e30f,t2=-1e30f,t3=-1e30f,t4=-1e30f,t5=-1e30f,t6=-1e30f,t7=-1e30f;
    int   i0=0,i1=0,i2=0,i3=0,i4=0,i5=0,i6=0,i7=0;

    for (int t = 0; t < 7; t++) {
        __syncthreads();   // kt[t&1] ready; ss[(t-1)&1] fully written
        if (isScan) {
            if (t < 6) {
                const float* kbn = &d_k[(b*NN + kbase + (t+1)*64)*64];
                float* dstb = &ktb[((t+1)&1)*4352];
#pragma unroll
                for (int i = 0; i < 16; i++) {
                    int fi = i*64 + st;
                    int row = fi >> 4, cc = fi & 15;
                    unsigned int dst = (unsigned int)__cvta_generic_to_shared(&dstb[row*68 + cc*4]);
                    asm volatile("cp.async.cg.shared.global [%0], [%1], 16;"
                                 :: "r"(dst), "l"(kbn + row*64 + cc*4));
                }
                asm volatile("cp.async.commit_group;");
            }
            if (t >= 1) {
                const float* sr = &ssb[((t-1)&1)*4288 + st*67];
                int jb = kbase + (t-1)*64;
                for (int g = 0; g < 8; g++) {
                    float m8 = sr[g*8];
#pragma unroll
                    for (int e = 1; e < 8; e++) m8 = fmaxf(m8, sr[g*8 + e]);
                    if (m8 > t0) {
#pragma unroll
                        for (int e = 0; e < 8; e++) {
                            float v = sr[g*8 + e];
                            if (v > t0) {
                                t0 = v; i0 = jb + g*8 + e;
                                SWP(t0,t1,i0,i1) SWP(t1,t2,i1,i2) SWP(t2,t3,i2,i3) SWP(t3,t4,i3,i4)
                                SWP(t4,t5,i4,i5) SWP(t5,t6,i5,i6) SWP(t6,t7,i6,i7)
                            }
                        }
                    }
                }
            }
            if (t < 6) asm volatile("cp.async.wait_group 0;");
        } else {
            const float* kc = &ktb[(t&1)*4352];
            const float* qb = &qs[qg*4*68];
            u64 acc[32];
#pragma unroll
            for (int j = 0; j < 32; j++) acc[j] = 0ull;
#pragma unroll
            for (int c = 0; c < 16; c++) {
                ulonglong2 qv[4], kv[8];
#pragma unroll
                for (int qq = 0; qq < 4; qq++)
                    qv[qq] = *(const ulonglong2*)&qb[qq*68 + c*4];
#pragma unroll
                for (int kj = 0; kj < 8; kj++)
                    kv[kj] = *(const ulonglong2*)&kc[(kg + 8*kj)*68 + c*4];
#pragma unroll
                for (int qq = 0; qq < 4; qq++)
#pragma unroll
                    for (int kj = 0; kj < 8; kj++) {
                        acc[qq*8+kj] = ffma2(qv[qq].x, kv[kj].x, acc[qq*8+kj]);
                        acc[qq*8+kj] = ffma2(qv[qq].y, kv[kj].y, acc[qq*8+kj]);
                    }
            }
            float* sw = &ssb[(t&1)*4288];
#pragma unroll
            for (int qq = 0; qq < 4; qq++)
#pragma unroll
                for (int kj = 0; kj < 8; kj++) {
                    float lo, hi; upk(acc[qq*8+kj], lo, hi);
                    sw[(qg*4 + qq)*67 + kg + 8*kj] = (lo + hi) * 0.125f;
                }
        }
    }
    __syncthreads();   // ss buf (6&1)=0 complete
    if (isScan) {
        const float* sr = &ssb[0*4288 + st*67];
        int jb = kbase + 6*64;
        for (int g = 0; g < 8; g++) {
            float m8 = sr[g*8];
#pragma unroll
            for (int e = 1; e < 8; e++) m8 = fmaxf(m8, sr[g*8 + e]);
            if (m8 > t0) {
#pragma unroll
                for (int e = 0; e < 8; e++) {
                    float v = sr[g*8 + e];
                    if (v > t0) {
                        t0 = v; i0 = jb + g*8 + e;
                        SWP(t0,t1,i0,i1) SWP(t1,t2,i1,i2) SWP(t2,t3,i2,i3) SWP(t3,t4,i3,i4)
                        SWP(t4,t5,i4,i5) SWP(t5,t6,i5,i6) SWP(t6,t7,i6,i7)
                    }
                }
            }
        }
        int qtok = b*NN + q0 + st;
        float* cvp = &d_cv[qtok*56 + split*8];
        int*   cip = &d_ci[qtok*56 + split*8];
        cvp[0]=t0; cvp[1]=t1; cvp[2]=t2; cvp[3]=t3;
        cvp[4]=t4; cvp[5]=t5; cvp[6]=t6; cvp[7]=t7;
        cip[0]=i0; cip[1]=i1; cip[2]=i2; cip[3]=i3;
        cip[4]=i4; cip[5]=i5; cip[6]=i6; cip[7]=i7;
    }
}

// merge 7 split candidate lists per query -> global top-8 + softmax weights
__global__ __launch_bounds__(128) void k3m_merge()
{
    __shared__ float cv[64*57];
    __shared__ int   ci[64*57];
    int tid = threadIdx.x;
    int q0 = blockIdx.x * 64;
    for (int idx = tid; idx < 64*56; idx += 128) {
        int q = idx / 56, e = idx % 56;
        cv[q*57 + e] = d_cv[(q0 + q)*56 + e];
        ci[q*57 + e] = d_ci[(q0 + q)*56 + e];
    }
    __syncthreads();
    if (tid < 64) {
        int q = tid;
        int qtok = q0 + q;
        float tv[8]; int ti[8];
#pragma unroll
        for (int pass = 0; pass < 8; pass++) {
            float best = -1e30f; int bp = 0;
            for (int e = 0; e < 56; e++) {
                float v = cv[q*57 + e];
                if (v > best) { best = v; bp = e; }
            }
            tv[pass] = best; ti[pass] = ci[q*57 + bp]; cv[q*57 + bp] = -1e30f;
        }
        float m = fmaxf(tv[0], 0.f);
        float ex[8], se = 0.f;
#pragma unroll
        for (int t = 0; t < 8; t++) { ex[t] = __expf(tv[t] - m); se += ex[t]; }
        float em = __expf(-m);
        float invZ = 1.f / ((float)(NN - 8) * em + se);
        float bsv = em * invZ;
        d_bs[qtok] = bsv;
#pragma unroll
        for (int t = 0; t < 8; t++) {
            d_wd[qtok*8 + t] = ex[t]*invZ - bsv;
            d_wi[qtok*8 + t] = ti[t];
        }
    }
}

// gather output: g = bs*sum_v + sum_t wd_t * v[wi_t]
__global__ __launch_bounds__(128) void k3b_out()
{
    int tid = threadIdx.x;
    int b = blockIdx.y;
    int rr = tid >> 3;
    int c0 = (tid & 7) << 3;
    int tok = b*NN + blockIdx.x*16 + rr;
    float bsv = d_bs[tok];
    u64 bsv2 = pk2(bsv);
    u64 acc[4];
    const ulonglong2* sv = (const ulonglong2*)&d_sumv[b*64 + c0];
    {
        ulonglong2 s0 = sv[0], s1 = sv[1];
        acc[0] = fmul2(bsv2, s0.x); acc[1] = fmul2(bsv2, s0.y);
        acc[2] = fmul2(bsv2, s1.x); acc[3] = fmul2(bsv2, s1.y);
    }
#pragma unroll
    for (int t = 0; t < 8; t++) {
        u64 w2 = pk2(d_wd[tok*8 + t]);
        int jj = d_wi[tok*8 + t];
        const ulonglong2* vp = (const ulonglong2*)&d_v[(b*NN + jj)*64 + c0];
        ulonglong2 v0 = vp[0], v1 = vp[1];
        acc[0] = ffma2(w2, v0.x, acc[0]); acc[1] = ffma2(w2, v0.y, acc[1]);
        acc[2] = ffma2(w2, v1.x, acc[2]); acc[3] = ffma2(w2, v1.y, acc[3]);
    }
    u64* go = (u64*)&d_g[tok*64 + c0];
#pragma unroll
    for (int j = 0; j < 4; j++) go[j] = acc[j];
}

// dense 3x3 conv + proj(g) + LN(norm1) + residual -> x1, weights staged in smem
__global__ __launch_bounds__(256) void k4_convproj(const float* __restrict__ x,
                                                   const float* __restrict__ n1g,
                                                   const float* __restrict__ n1b,
                                                   const float* __restrict__ wproj,
                                                   const float* __restrict__ bproj,
                                                   const float* __restrict__ localb)
{
    __shared__ float patch[64*101];
    __shared__ float wsm[4*9*64];
    int tid = threadIdx.x;
    int tx = blockIdx.x, ty = blockIdx.y, b = blockIdx.z;
    for (int idx = tid; idx < 6400; idx += 256) {
        int c = idx & 63, pos = idx >> 6;
        int py = pos / 10, px = pos % 10;
        int gy = ty*8 + py - 1, gx = tx*8 + px - 1;
        float v = 0.f;
        if (gy >= 0 && gy < 56 && gx >= 0 && gx < 56)
            v = x[(b*NN + gy*56 + gx)*64 + c];
        patch[c*101 + pos] = v;
    }
    int p = tid >> 2, c0 = (tid & 3) << 4;
    int py = p >> 3, px = p & 7;
    u64 acc[8];
#pragma unroll
    for (int j = 0; j < 8; j++)
        acc[j] = pk(localb[c0+2*j] + bproj[c0+2*j], localb[c0+2*j+1] + bproj[c0+2*j+1]);

    for (int ch = 0; ch < 16; ch++) {
        __syncthreads();
        for (int idx = tid; idx < 2304; idx += 256)
            wsm[idx] = d_lwT[ch*2304 + idx];
        __syncthreads();
#pragma unroll
        for (int cil = 0; cil < 4; cil++) {
            const float* prow = &patch[(ch*4 + cil)*101];
#pragma unroll
            for (int ky = 0; ky < 3; ky++)
#pragma unroll
            for (int kx = 0; kx < 3; kx++) {
                u64 pv2 = pk2(prow[(py + ky)*10 + px + kx]);
                const ulonglong2* wr = (const ulonglong2*)&wsm[(cil*9 + ky*3 + kx)*64 + c0];
                ulonglong2 wa = wr[0], wb = wr[1], wc = wr[2], wdd = wr[3];
                acc[0] = ffma2(pv2, wa.x, acc[0]); acc[1] = ffma2(pv2, wa.y, acc[1]);
                acc[2] = ffma2(pv2, wb.x, acc[2]); acc[3] = ffma2(pv2, wb.y, acc[3]);
                acc[4] = ffma2(pv2, wc.x, acc[4]); acc[5] = ffma2(pv2, wc.y, acc[5]);
                acc[6] = ffma2(pv2, wdd.x, acc[6]); acc[7] = ffma2(pv2, wdd.y, acc[7]);
            }
        }
    }
    int tokk = b*NN + (ty*8 + py)*56 + tx*8 + px;
    for (int kc = 0; kc < 4; kc++) {
        __syncthreads();
        for (int idx = tid; idx < 1024; idx += 256)
            wsm[idx] = wproj[kc*1024 + idx];
        __syncthreads();
        float4 g4[4];
        const float4* gp = (const float4*)&d_g[tokk*64 + kc*16];
#pragma unroll
        for (int j = 0; j < 4; j++) g4[j] = gp[j];
#pragma unroll
        for (int k = 0; k < 16; k++) {
            float gv = ((const float*)g4)[k];
            u64 gv2 = pk2(gv);
            const ulonglong2* wr = (const ulonglong2*)&wsm[k*64 + c0];
            ulonglong2 wa = wr[0], wb = wr[1], wc = wr[2], wdd = wr[3];
            acc[0] = ffma2(gv2, wa.x, acc[0]); acc[1] = ffma2(gv2, wa.y, acc[1]);
            acc[2] = ffma2(gv2, wb.x, acc[2]); acc[3] = ffma2(gv2, wb.y, acc[3]);
            acc[4] = ffma2(gv2, wc.x, acc[4]); acc[5] = ffma2(gv2, wc.y, acc[5]);
            acc[6] = ffma2(gv2, wdd.x, acc[6]); acc[7] = ffma2(gv2, wdd.y, acc[7]);
        }
    }
    float va[16];
#pragma unroll
    for (int j = 0; j < 8; j++) upk(acc[j], va[2*j], va[2*j+1]);
    float s1 = 0.f, s2 = 0.f;
#pragma unroll
    for (int j = 0; j < 16; j++) { s1 += va[j]; s2 += va[j]*va[j]; }
    s1 += __shfl_xor_sync(0xffffffffu, s1, 1);
    s2 += __shfl_xor_sync(0xffffffffu, s2, 1);
    s1 += __shfl_xor_sync(0xffffffffu, s1, 2);
    s2 += __shfl_xor_sync(0xffffffffu, s2, 2);
    float mean = s1 * (1.f/64.f);
    float rs = rsqrtf(s2*(1.f/64.f) - mean*mean + 1e-5f);
#pragma unroll
    for (int j = 0; j < 16; j++) {
        int c = c0 + j;
        float xv = patch[c*101 + (py + 1)*10 + px + 1];
        d_x1[tokk*64 + c] = xv + (va[j] - mean) * rs * n1g[c] + n1b[c];
    }
}

__global__ __launch_bounds__(256) void k5a_ln2(const float* __restrict__ n2g,
                                               const float* __restrict__ n2b)
{
    __shared__ float xs[32*65];
    int tid = threadIdx.x;
    int tok0 = blockIdx.x * 32;
    for (int idx = tid; idx < 2048; idx += 256) {
        int t = idx >> 6, c = idx & 63;
        xs[t*65 + c] = d_x1[(tok0 + t)*64 + c];
    }
    __syncthreads();
    int t = tid >> 3, fg = tid & 7;
    float vals[8], s1 = 0.f, s2 = 0.f;
#pragma unroll
    for (int i = 0; i < 8; i++) {
        float v = xs[t*65 + fg*8 + i];
        vals[i] = v; s1 += v; s2 += v*v;
    }
#pragma unroll
    for (int o = 1; o < 8; o <<= 1) {
        s1 += __shfl_xor_sync(0xffffffffu, s1, o);
        s2 += __shfl_xor_sync(0xffffffffu, s2, o);
    }
    float mean = s1 * (1.f/64.f);
    float rs = rsqrtf(s2*(1.f/64.f) - mean*mean + 1e-5f);
#pragma unroll
    for (int i = 0; i < 8; i++) {
        int c = fg*8 + i;
        d_xn2[(tok0 + t)*64 + c] = (vals[i] - mean) * rs * n2g[c] + n2b[c];
    }
}

// depthwise 3x3 + 5x5 (mult 4): thread = (channel, mult), weights in registers
__global__ __launch_bounds__(128) void k5b_dw(const float* __restrict__ w3,
                                              const float* __restrict__ b3,
                                              const float* __restrict__ w5,
                                              const float* __restrict__ b5)
{
    __shared__ float patch[32*145];
    int tid = threadIdx.x;
    int tx = blockIdx.x, ty = blockIdx.y;
    int bz = blockIdx.z;
    int b = bz >> 1, half = bz & 1;
    for (int idx = tid; idx < 4608; idx += 128) {
        int c = idx / 144, pos = idx % 144;
        int py = pos / 12, px = pos % 12;
        int gy = ty*8 + py - 2, gx = tx*8 + px - 2;
        float v = 0.f;
        if (gy >= 0 && gy < 56 && gx >= 0 && gx < 56)
            v = d_xn2[(b*NN + gy*56 + gx)*64 + half*32 + c];
        patch[c*145 + pos] = v;
    }
    __syncthreads();
    int e = tid & 3, c = tid >> 2;
    int o = (half*32 + c)*4 + e;
    float w3r[9], w5r[25];
#pragma unroll
    for (int i = 0; i < 9; i++)  w3r[i] = w3[o*9 + i];
#pragma unroll
    for (int i = 0; i < 25; i++) w5r[i] = w5[o*25 + i];
    float b3r = b3[o], b5r = b5[o];
    const float* pr = &patch[c*145];
    int tokbase = b*NN + ty*8*56 + tx*8;
    for (int p = 0; p < 64; p++) {
        int py = p >> 3, px = p & 7;
        float n[25];
#pragma unroll
        for (int ky = 0; ky < 5; ky++)
#pragma unroll
        for (int kx = 0; kx < 5; kx++)
            n[ky*5+kx] = pr[(py + ky)*12 + px + kx];
        float a3 = b3r;
#pragma unroll
        for (int ky = 0; ky < 3; ky++)
#pragma unroll
        for (int kx = 0; kx < 3; kx++)
            a3 = fmaf(n[(ky+1)*5 + kx+1], w3r[ky*3+kx], a3);
        float a5 = b5r;
#pragma unroll
        for (int i = 0; i < 25; i++) a5 = fmaf(n[i], w5r[i], a5);
        int tok = tokbase + py*56 + px;
        d_cat[tok*512 + o]       = a3;
        d_cat[tok*512 + 256 + o] = a5;
    }
}

// 1x1 mix (512->64) + residual, weights tiled through smem, 2 tokens/thread
__global__ __launch_bounds__(128) void k5c_mix(const float* __restrict__ b1,
                                               float* __restrict__ out)
{
    __shared__ float cs[16*512];
    __shared__ float wsm[64*64];
    int tid = threadIdx.x;
    int tok0 = blockIdx.x * 16;
    for (int idx = tid; idx < 8192; idx += 128)
        cs[idx] = d_cat[tok0*512 + idx];
    int fg = tid & 15, ts = tid >> 4;
    int o0 = fg * 4;
    u64 a00 = pk(b1[o0], b1[o0+1]);
    u64 a01 = pk(b1[o0+2], b1[o0+3]);
    u64 a10 = a00, a11 = a01;
    for (int kt = 0; kt < 8; kt++) {
        __syncthreads();
        for (int idx = tid; idx < 4096; idx += 128)
            wsm[idx] = d_w1t[kt*4096 + idx];
        __syncthreads();
        const float* cA = &cs[ts*512 + kt*64];
        const float* cB = &cs[(ts+8)*512 + kt*64];
#pragma unroll 8
        for (int k = 0; k < 64; k++) {
            ulonglong2 w = *(const ulonglong2*)&wsm[k*64 + o0];
            u64 ca = pk2(cA[k]);
            u64 cb = pk2(cB[k]);
            a00 = ffma2(ca, w.x, a00); a01 = ffma2(ca, w.y, a01);
            a10 = ffma2(cb, w.x, a10); a11 = ffma2(cb, w.y, a11);
        }
    }
    float r0, r1, r2, r3;
    int tokA = tok0 + ts, tokB = tok0 + ts + 8;
    upk(a00, r0, r1); upk(a01, r2, r3);
    {
        float4 xv = *(const float4*)&d_x1[tokA*64 + o0];
        float4 ov; ov.x = xv.x + r0; ov.y = xv.y + r1; ov.z = xv.z + r2; ov.w = xv.w + r3;
        *(float4*)&out[tokA*64 + o0] = ov;
    }
    upk(a10, r0, r1); upk(a11, r2, r3);
    {
        float4 xv = *(const float4*)&d_x1[tokB*64 + o0];
        float4 ov; ov.x = xv.x + r0; ov.y = xv.y + r1; ov.z = xv.z + r2; ov.w = xv.w + r3;
        *(float4*)&out[tokB*64 + o0] = ov;
    }
}

extern "C" void kernel_launch(void* const* d_in, const int* in_sizes, int n_in,
                              void* d_out, int out_size)
{
    const float* x      = (const float*)d_in[0];
    const float* n1g    = (const float*)d_in[1];
    const float* n1b    = (const float*)d_in[2];
    const float* wq     = (const float*)d_in[3];
    const float* bq     = (const float*)d_in[4];
    const float* wkv    = (const float*)d_in[5];
    const float* bkv    = (const float*)d_in[6];
    const float* wproj  = (const float*)d_in[7];
    const float* bproj  = (const float*)d_in[8];
    const float* lw     = (const float*)d_in[9];
    const float* lb     = (const float*)d_in[10];
    const float* n2g    = (const float*)d_in[11];
    const float* n2b    = (const float*)d_in[12];
    const float* w3     = (const float*)d_in[13];
    const float* b3     = (const float*)d_in[14];
    const float* w5     = (const float*)d_in[15];
    const float* b5     = (const float*)d_in[16];
    const float* w1     = (const float*)d_in[17];
    const float* b1     = (const float*)d_in[18];
    float* out = (float*)d_out;

    cudaFuncSetAttribute(k3a_score, cudaFuncAttributeMaxDynamicSharedMemorySize, K3A_SMEM);

    k0_prep<<<321, 256>>>(wq, bq, wkv, bkv, lw, w1);     // 1
    k1_lnqkv<<<392, 256>>>(x, n1g, n1b);                 // 2
    k2a_sumv<<<dim3(4, 8), 256>>>();                     // 3
    k3a_score<<<dim3(49, KSPLIT, NB), 192, K3A_SMEM>>>();// 4  <- profiled slot
    k2b_sumv<<<4, 256>>>();                              // 5
    k3m_merge<<<196, 128>>>();                           // 6
    k3b_out<<<dim3(196, 4), 128>>>();                    // 7
    k4_convproj<<<dim3(7, 7, 4), 256>>>(x, n1g, n1b, wproj, bproj, lb); // 8
    k5a_ln2<<<392, 256>>>(n2g, n2b);                     // 9
    k5b_dw<<<dim3(7, 7, 8), 128>>>(w3, b3, w5, b5);      // 10
    k5c_mix<<<784, 128>>>(b1, out);                      // 11
}

// round 14
// speedup vs baseline: 1.3434x; 1.3434x over previous
#include <cuda_runtime.h>
#include <cuda_bf16.h>

#define NB 4
#define NN 3136
#define NTOK (NB*NN)
typedef unsigned long long u64;

__device__ __nv_bfloat16 d_qh[NTOK*64];
__device__ __nv_bfloat16 d_kh[NTOK*64];
__device__ float d_v[NTOK*64];
__device__ float d_g[NTOK*64];
__device__ float d_x1[NTOK*64];
__device__ float d_xn2[NTOK*64];
__device__ float d_cat[NTOK*512];
__device__ float d_sumv[NB*64];
__device__ float d_svp[NB*32*64];
__device__ float d_Wc[64*192];
__device__ float d_Wb[192];
__device__ float d_lwT[576*64];
__device__ float d_w1t[512*64];
__device__ float d_wd[NTOK*8];
__device__ int   d_wi[NTOK*8];
__device__ float d_bs[NTOK];
__device__ float d_cv[NTOK*56];
__device__ int   d_ci[NTOK*56];

__device__ __forceinline__ u64 ffma2(u64 a, u64 b, u64 c) {
    u64 d; asm("fma.rn.f32x2 %0, %1, %2, %3;" : "=l"(d) : "l"(a), "l"(b), "l"(c)); return d;
}
__device__ __forceinline__ u64 fmul2(u64 a, u64 b) {
    u64 d; asm("mul.rn.f32x2 %0, %1, %2;" : "=l"(d) : "l"(a), "l"(b)); return d;
}
__device__ __forceinline__ u64 pk2(float v) {
    u64 d; asm("mov.b64 %0, {%1, %1};" : "=l"(d) : "f"(v)); return d;
}
__device__ __forceinline__ u64 pk(float lo, float hi) {
    u64 d; asm("mov.b64 %0, {%1, %2};" : "=l"(d) : "f"(lo), "f"(hi)); return d;
}
__device__ __forceinline__ void upk(u64 v, float& lo, float& hi) {
    asm("mov.b64 {%0, %1}, %2;" : "=f"(lo), "=f"(hi) : "l"(v));
}

__global__ void k0_prep(const float* __restrict__ wq, const float* __restrict__ bq,
                        const float* __restrict__ wkv, const float* __restrict__ bkv,
                        const float* __restrict__ lw, const float* __restrict__ w1)
{
    int i = blockIdx.x * 256 + threadIdx.x;
    if (i < 64*192) {
        int k = i / 192, f = i % 192;
        d_Wc[i] = (f < 64) ? wq[k*64 + f] : wkv[k*128 + (f - 64)];
    }
    int j = i - 64*192;
    if (j >= 0 && j < 192) d_Wb[j] = (j < 64) ? bq[j] : bkv[j - 64];
    int l = i - (64*192 + 192);
    if (l >= 0 && l < 576*64) d_lwT[l] = lw[(l % 64)*576 + (l / 64)];
    int m = i - (64*192 + 192 + 576*64);
    if (m >= 0 && m < 512*64) d_w1t[m] = w1[(m % 64)*512 + (m / 64)];
}

// LN1 + fused QKV projection: q,k emitted as bf16; v as fp32
__global__ __launch_bounds__(256) void k1_lnqkv(const float* __restrict__ x,
                                                const float* __restrict__ n1g,
                                                const float* __restrict__ n1b)
{
    __shared__ float xs[32*65];
    int tid = threadIdx.x;
    int tok0 = blockIdx.x * 32;
    for (int idx = tid; idx < 2048; idx += 256) {
        int t = idx >> 6, c = idx & 63;
        xs[t*65 + c] = x[(tok0 + t)*64 + c];
    }
    __syncthreads();
    int t = tid >> 3, fg = tid & 7;
    float vals[8], s1 = 0.f, s2 = 0.f;
#pragma unroll
    for (int i = 0; i < 8; i++) {
        float v = xs[t*65 + fg*8 + i];
        vals[i] = v; s1 += v; s2 += v*v;
    }
#pragma unroll
    for (int o = 1; o < 8; o <<= 1) {
        s1 += __shfl_xor_sync(0xffffffffu, s1, o);
        s2 += __shfl_xor_sync(0xffffffffu, s2, o);
    }
    float mean = s1 * (1.f/64.f);
    float rs = rsqrtf(s2*(1.f/64.f) - mean*mean + 1e-5f);
#pragma unroll
    for (int i = 0; i < 8; i++) {
        int c = fg*8 + i;
        xs[t*65 + c] = (vals[i] - mean) * rs * n1g[c] + n1b[c];
    }
    __syncthreads();
    int f0 = fg * 24;
    u64 acc[12];
#pragma unroll
    for (int j = 0; j < 12; j++) acc[j] = pk(d_Wb[f0 + 2*j], d_Wb[f0 + 2*j + 1]);
#pragma unroll 4
    for (int k = 0; k < 64; k++) {
        u64 xv2 = pk2(xs[t*65 + k]);
        const ulonglong2* wr = (const ulonglong2*)&d_Wc[k*192 + f0];
#pragma unroll
        for (int j2 = 0; j2 < 6; j2++) {
            ulonglong2 w = wr[j2];
            acc[j2*2+0] = ffma2(xv2, w.x, acc[j2*2+0]);
            acc[j2*2+1] = ffma2(xv2, w.y, acc[j2*2+1]);
        }
    }
    int tok = tok0 + t;
#pragma unroll
    for (int j = 0; j < 12; j++) {
        float lo, hi; upk(acc[j], lo, hi);
        int f = f0 + 2*j;
#pragma unroll
        for (int e = 0; e < 2; e++) {
            int ff = f + e;
            float v = e ? hi : lo;
            if (ff < 64)       d_qh[tok*64 + ff] = __float2bfloat16(v);
            else if (ff < 128) d_kh[tok*64 + ff - 64] = __float2bfloat16(v);
            else               d_v[tok*64 + ff - 128] = v;
        }
    }
}

__global__ void k2a_sumv()
{
    int b = blockIdx.x, oct = blockIdx.y;
    int c = threadIdx.x & 63, sg = threadIdx.x >> 6;
    float a = 0.f;
    int base = b*NN + oct*392 + sg*98;
#pragma unroll 4
    for (int j = 0; j < 98; j++) a += d_v[(base + j)*64 + c];
    d_svp[(b*32 + oct*4 + sg)*64 + c] = a;
}
__global__ void k2b_sumv()
{
    __shared__ float red[4][64];
    int b = blockIdx.x;
    int c = threadIdx.x & 63, part = threadIdx.x >> 6;
    float a = 0.f;
#pragma unroll
    for (int s = 0; s < 8; s++) a += d_svp[(b*32 + part*8 + s)*64 + c];
    red[part][c] = a;
    __syncthreads();
    if (part == 0)
        d_sumv[b*64 + c] = (red[0][c] + red[1][c]) + (red[2][c] + red[3][c]);
}

#define SWP(a,b,ia,ib) if (a > b) { float tf_=a; a=b; b=tf_; int ti_=ia; ia=ib; ib=ti_; }
#define KSPLIT 7
#define TPS 448
// smem: qh 64*72*2=9216 | kt 2*9216=18432 | ss 64*66*4=16896 -> 44544
#define K3A_SMEM 44544

// Tensor-core scorer: 64 queries x 448 keys per block (7 tiles of 64).
// 4 warps, each m16 x n64 via mma.sync.m16n8k16 bf16 (A=q row-major,
// B=k tile [key][ch] read non-trans => col-major operand).
__global__ __launch_bounds__(128, 4) void k3a_score()
{
    extern __shared__ __align__(16) char smem[];
    __nv_bfloat16* qh = (__nv_bfloat16*)smem;           // 64 x 72
    __nv_bfloat16* kt = (__nv_bfloat16*)(smem + 9216);  // 2 x (64 x 72)
    float* ss = (float*)(smem + 27648);                 // 64 x 66
    int tid = threadIdx.x;
    int lane = tid & 31, w = tid >> 5;
    int b = blockIdx.z, split = blockIdx.y;
    int q0 = blockIdx.x * 64;
    int kbase = split * TPS;

    // q tile -> smem (stride 72 bf16 = 144B rows, 16B-chunk conflict-free)
#pragma unroll
    for (int i = 0; i < 4; i++) {
        int fi = i*128 + tid;
        int row = fi >> 3, ch = fi & 7;
        *(float4*)&qh[row*72 + ch*8] =
            *(const float4*)&d_qh[(b*NN + q0 + row)*64 + ch*8];
    }
    // prefetch k tile 0 -> buf 0
    {
        const __nv_bfloat16* src0 = &d_kh[(b*NN + kbase)*64];
#pragma unroll
        for (int i = 0; i < 4; i++) {
            int fi = i*128 + tid;
            int row = fi >> 3, ch = fi & 7;
            unsigned int dst = (unsigned int)__cvta_generic_to_shared(&kt[row*72 + ch*8]);
            asm volatile("cp.async.cg.shared.global [%0], [%1], 16;"
                         :: "r"(dst), "l"(src0 + row*64 + ch*8));
        }
        asm volatile("cp.async.commit_group;");
    }

    int qw = w * 16;
    unsigned int a_base = (unsigned int)__cvta_generic_to_shared(
        &qh[(qw + (lane & 15))*72 + (lane >> 4)*8]);
    int lane16 = lane & 15;
    unsigned int b_off = (unsigned int)((lane16 & 7)*72 + (lane16 >> 3)*8) * 2;

    int sq = tid >> 1, sp = tid & 1;
    float t0=-1e30f,t1=-1e30f,t2=-1e30f,t3=-1e30f,t4=-1e30f,t5=-1e30f,t6=-1e30f,t7=-1e30f;
    int   i0=0,i1=0,i2=0,i3=0,i4=0,i5=0,i6=0,i7=0;

    for (int t = 0; t < 7; t++) {
        if (t < 6) {
            const __nv_bfloat16* srcn = &d_kh[(b*NN + kbase + (t+1)*64)*64];
            __nv_bfloat16* dstb = &kt[((t+1)&1)*4608];
#pragma unroll
            for (int i = 0; i < 4; i++) {
                int fi = i*128 + tid;
                int row = fi >> 3, ch = fi & 7;
                unsigned int dst = (unsigned int)__cvta_generic_to_shared(&dstb[row*72 + ch*8]);
                asm volatile("cp.async.cg.shared.global [%0], [%1], 16;"
                             :: "r"(dst), "l"(srcn + row*64 + ch*8));
            }
            asm volatile("cp.async.commit_group;");
            asm volatile("cp.async.wait_group 1;");
        } else {
            asm volatile("cp.async.wait_group 0;");
        }
        __syncthreads();   // kt[t&1] ready; scan(t-1) done -> ss reusable

        unsigned int kta = (unsigned int)__cvta_generic_to_shared(&kt[(t&1)*4608]);
        float acc[8][4];
#pragma unroll
        for (int n = 0; n < 8; n++)
#pragma unroll
            for (int e = 0; e < 4; e++) acc[n][e] = 0.f;

#pragma unroll
        for (int s = 0; s < 4; s++) {
            unsigned int ra0, ra1, ra2, ra3;
            asm volatile("ldmatrix.sync.aligned.m8n8.x4.shared.b16 {%0,%1,%2,%3}, [%4];"
                         : "=r"(ra0), "=r"(ra1), "=r"(ra2), "=r"(ra3)
                         : "r"(a_base + s*32));
#pragma unroll
            for (int n = 0; n < 8; n++) {
                unsigned int rb0, rb1;
                asm volatile("ldmatrix.sync.aligned.m8n8.x2.shared.b16 {%0,%1}, [%2];"
                             : "=r"(rb0), "=r"(rb1)
                             : "r"(kta + b_off + (unsigned int)(n*1152 + s*32)));
                asm volatile("mma.sync.aligned.m16n8k16.row.col.f32.bf16.bf16.f32 "
                             "{%0,%1,%2,%3}, {%4,%5,%6,%7}, {%8,%9}, {%0,%1,%2,%3};"
                             : "+f"(acc[n][0]), "+f"(acc[n][1]),
                               "+f"(acc[n][2]), "+f"(acc[n][3])
                             : "r"(ra0), "r"(ra1), "r"(ra2), "r"(ra3),
                               "r"(rb0), "r"(rb1));
            }
        }
        // writeback scores (scaled)
        {
            int g = lane >> 2, col = (lane & 3)*2;
#pragma unroll
            for (int n = 0; n < 8; n++) {
                *(float2*)&ss[(qw+g)*66 + n*8 + col] =
                    make_float2(acc[n][0]*0.125f, acc[n][1]*0.125f);
                *(float2*)&ss[(qw+g+8)*66 + n*8 + col] =
                    make_float2(acc[n][2]*0.125f, acc[n][3]*0.125f);
            }
        }
        __syncthreads();
        // scan: 2 threads per query, 32 keys each, 8-group max prefilter
        {
            const float* sr = &ss[sq*66 + sp];
            int jb = kbase + t*64 + sp;
#pragma unroll
            for (int g8 = 0; g8 < 4; g8++) {
                float m8 = sr[2*(g8*8)];
#pragma unroll
                for (int e = 1; e < 8; e++) m8 = fmaxf(m8, sr[2*(g8*8 + e)]);
                if (m8 > t0) {
#pragma unroll
                    for (int e = 0; e < 8; e++) {
                        float v = sr[2*(g8*8 + e)];
                        if (v > t0) {
                            t0 = v; i0 = jb + 2*(g8*8 + e);
                            SWP(t0,t1,i0,i1) SWP(t1,t2,i1,i2) SWP(t2,t3,i2,i3) SWP(t3,t4,i3,i4)
                            SWP(t4,t5,i4,i5) SWP(t5,t6,i5,i6) SWP(t6,t7,i6,i7)
                        }
                    }
                }
            }
        }
    }
    __syncthreads();

    // merge 2 partials/query (reuse ss region), write split candidates
    float* mvv = ss;
    int*   mii = (int*)(ss + 1024);
    int b8 = tid*8;
    mvv[b8+0]=t0; mvv[b8+1]=t1; mvv[b8+2]=t2; mvv[b8+3]=t3;
    mvv[b8+4]=t4; mvv[b8+5]=t5; mvv[b8+6]=t6; mvv[b8+7]=t7;
    mii[b8+0]=i0; mii[b8+1]=i1; mii[b8+2]=i2; mii[b8+3]=i3;
    mii[b8+4]=i4; mii[b8+5]=i5; mii[b8+6]=i6; mii[b8+7]=i7;
    __syncthreads();
    if (tid < 64) {
        int q = tid;
        int base = q*16;
        int qtok = b*NN + q0 + q;
#pragma unroll
        for (int pass = 0; pass < 8; pass++) {
            float best = -1e30f; int bp = base;
#pragma unroll
            for (int e = 0; e < 16; e++) {
                float v = mvv[base + e];
                if (v > best) { best = v; bp = base + e; }
            }
            d_cv[qtok*56 + split*8 + pass] = best;
            d_ci[qtok*56 + split*8 + pass] = mii[bp];
            mvv[bp] = -1e30f;
        }
    }
}

// merge 7 split candidate lists per query -> global top-8 + softmax weights
__global__ __launch_bounds__(128) void k3m_merge()
{
    __shared__ float cv[64*57];
    __shared__ int   ci[64*57];
    int tid = threadIdx.x;
    int q0 = blockIdx.x * 64;
    for (int idx = tid; idx < 64*56; idx += 128) {
        int q = idx / 56, e = idx % 56;
        cv[q*57 + e] = d_cv[(q0 + q)*56 + e];
        ci[q*57 + e] = d_ci[(q0 + q)*56 + e];
    }
    __syncthreads();
    if (tid < 64) {
        int q = tid;
        int qtok = q0 + q;
        float tv[8]; int ti[8];
#pragma unroll
        for (int pass = 0; pass < 8; pass++) {
            float best = -1e30f; int bp = 0;
            for (int e = 0; e < 56; e++) {
                float v = cv[q*57 + e];
                if (v > best) { best = v; bp = e; }
            }
            tv[pass] = best; ti[pass] = ci[q*57 + bp]; cv[q*57 + bp] = -1e30f;
        }
        float m = fmaxf(tv[0], 0.f);
        float ex[8], se = 0.f;
#pragma unroll
        for (int t = 0; t < 8; t++) { ex[t] = __expf(tv[t] - m); se += ex[t]; }
        float em = __expf(-m);
        float invZ = 1.f / ((float)(NN - 8) * em + se);
        float bsv = em * invZ;
        d_bs[qtok] = bsv;
#pragma unroll
        for (int t = 0; t < 8; t++) {
            d_wd[qtok*8 + t] = ex[t]*invZ - bsv;
            d_wi[qtok*8 + t] = ti[t];
        }
    }
}

// gather output: g = bs*sum_v + sum_t wd_t * v[wi_t]
__global__ __launch_bounds__(128) void k3b_out()
{
    int tid = threadIdx.x;
    int b = blockIdx.y;
    int rr = tid >> 3;
    int c0 = (tid & 7) << 3;
    int tok = b*NN + blockIdx.x*16 + rr;
    float bsv = d_bs[tok];
    u64 bsv2 = pk2(bsv);
    u64 acc[4];
    const ulonglong2* sv = (const ulonglong2*)&d_sumv[b*64 + c0];
    {
        ulonglong2 s0 = sv[0], s1 = sv[1];
        acc[0] = fmul2(bsv2, s0.x); acc[1] = fmul2(bsv2, s0.y);
        acc[2] = fmul2(bsv2, s1.x); acc[3] = fmul2(bsv2, s1.y);
    }
#pragma unroll
    for (int t = 0; t < 8; t++) {
        u64 w2 = pk2(d_wd[tok*8 + t]);
        int jj = d_wi[tok*8 + t];
        const ulonglong2* vp = (const ulonglong2*)&d_v[(b*NN + jj)*64 + c0];
        ulonglong2 v0 = vp[0], v1 = vp[1];
        acc[0] = ffma2(w2, v0.x, acc[0]); acc[1] = ffma2(w2, v0.y, acc[1]);
        acc[2] = ffma2(w2, v1.x, acc[2]); acc[3] = ffma2(w2, v1.y, acc[3]);
    }
    u64* go = (u64*)&d_g[tok*64 + c0];
#pragma unroll
    for (int j = 0; j < 4; j++) go[j] = acc[j];
}

// dense 3x3 conv + proj(g) + LN(norm1) + residual -> x1, weights staged in smem
__global__ __launch_bounds__(256) void k4_convproj(const float* __restrict__ x,
                                                   const float* __restrict__ n1g,
                                                   const float* __restrict__ n1b,
                                                   const float* __restrict__ wproj,
                                                   const float* __restrict__ bproj,
                                                   const float* __restrict__ localb)
{
    __shared__ float patch[64*101];
    __shared__ float wsm[4*9*64];
    int tid = threadIdx.x;
    int tx = blockIdx.x, ty = blockIdx.y, b = blockIdx.z;
    for (int idx = tid; idx < 6400; idx += 256) {
        int c = idx & 63, pos = idx >> 6;
        int py = pos / 10, px = pos % 10;
        int gy = ty*8 + py - 1, gx = tx*8 + px - 1;
        float v = 0.f;
        if (gy >= 0 && gy < 56 && gx >= 0 && gx < 56)
            v = x[(b*NN + gy*56 + gx)*64 + c];
        patch[c*101 + pos] = v;
    }
    int p = tid >> 2, c0 = (tid & 3) << 4;
    int py = p >> 3, px = p & 7;
    u64 acc[8];
#pragma unroll
    for (int j = 0; j < 8; j++)
        acc[j] = pk(localb[c0+2*j] + bproj[c0+2*j], localb[c0+2*j+1] + bproj[c0+2*j+1]);

    for (int ch = 0; ch < 16; ch++) {
        __syncthreads();
        for (int idx = tid; idx < 2304; idx += 256)
            wsm[idx] = d_lwT[ch*2304 + idx];
        __syncthreads();
#pragma unroll
        for (int cil = 0; cil < 4; cil++) {
            const float* prow = &patch[(ch*4 + cil)*101];
#pragma unroll
            for (int ky = 0; ky < 3; ky++)
#pragma unroll
            for (int kx = 0; kx < 3; kx++) {
                u64 pv2 = pk2(prow[(py + ky)*10 + px + kx]);
                const ulonglong2* wr = (const ulonglong2*)&wsm[(cil*9 + ky*3 + kx)*64 + c0];
                ulonglong2 wa = wr[0], wb = wr[1], wc = wr[2], wdd = wr[3];
                acc[0] = ffma2(pv2, wa.x, acc[0]); acc[1] = ffma2(pv2, wa.y, acc[1]);
                acc[2] = ffma2(pv2, wb.x, acc[2]); acc[3] = ffma2(pv2, wb.y, acc[3]);
                acc[4] = ffma2(pv2, wc.x, acc[4]); acc[5] = ffma2(pv2, wc.y, acc[5]);
                acc[6] = ffma2(pv2, wdd.x, acc[6]); acc[7] = ffma2(pv2, wdd.y, acc[7]);
            }
        }
    }
    int tokk = b*NN + (ty*8 + py)*56 + tx*8 + px;
    for (int kc = 0; kc < 4; kc++) {
        __syncthreads();
        for (int idx = tid; idx < 1024; idx += 256)
            wsm[idx] = wproj[kc*1024 + idx];
        __syncthreads();
        float4 g4[4];
        const float4* gp = (const float4*)&d_g[tokk*64 + kc*16];
#pragma unroll
        for (int j = 0; j < 4; j++) g4[j] = gp[j];
#pragma unroll
        for (int k = 0; k < 16; k++) {
            float gv = ((const float*)g4)[k];
            u64 gv2 = pk2(gv);
            const ulonglong2* wr = (const ulonglong2*)&wsm[k*64 + c0];
            ulonglong2 wa = wr[0], wb = wr[1], wc = wr[2], wdd = wr[3];
            acc[0] = ffma2(gv2, wa.x, acc[0]); acc[1] = ffma2(gv2, wa.y, acc[1]);
            acc[2] = ffma2(gv2, wb.x, acc[2]); acc[3] = ffma2(gv2, wb.y, acc[3]);
            acc[4] = ffma2(gv2, wc.x, acc[4]); acc[5] = ffma2(gv2, wc.y, acc[5]);
            acc[6] = ffma2(gv2, wdd.x, acc[6]); acc[7] = ffma2(gv2, wdd.y, acc[7]);
        }
    }
    float va[16];
#pragma unroll
    for (int j = 0; j < 8; j++) upk(acc[j], va[2*j], va[2*j+1]);
    float s1 = 0.f, s2 = 0.f;
#pragma unroll
    for (int j = 0; j < 16; j++) { s1 += va[j]; s2 += va[j]*va[j]; }
    s1 += __shfl_xor_sync(0xffffffffu, s1, 1);
    s2 += __shfl_xor_sync(0xffffffffu, s2, 1);
    s1 += __shfl_xor_sync(0xffffffffu, s1, 2);
    s2 += __shfl_xor_sync(0xffffffffu, s2, 2);
    float mean = s1 * (1.f/64.f);
    float rs = rsqrtf(s2*(1.f/64.f) - mean*mean + 1e-5f);
#pragma unroll
    for (int j = 0; j < 16; j++) {
        int c = c0 + j;
        float xv = patch[c*101 + (py + 1)*10 + px + 1];
        d_x1[tokk*64 + c] = xv + (va[j] - mean) * rs * n1g[c] + n1b[c];
    }
}

__global__ __launch_bounds__(256) void k5a_ln2(const float* __restrict__ n2g,
                                               const float* __restrict__ n2b)
{
    __shared__ float xs[32*65];
    int tid = threadIdx.x;
    int tok0 = blockIdx.x * 32;
    for (int idx = tid; idx < 2048; idx += 256) {
        int t = idx >> 6, c = idx & 63;
        xs[t*65 + c] = d_x1[(tok0 + t)*64 + c];
    }
    __syncthreads();
    int t = tid >> 3, fg = tid & 7;
    float vals[8], s1 = 0.f, s2 = 0.f;
#pragma unroll
    for (int i = 0; i < 8; i++) {
        float v = xs[t*65 + fg*8 + i];
        vals[i] = v; s1 += v; s2 += v*v;
    }
#pragma unroll
    for (int o = 1; o < 8; o <<= 1) {
        s1 += __shfl_xor_sync(0xffffffffu, s1, o);
        s2 += __shfl_xor_sync(0xffffffffu, s2, o);
    }
    float mean = s1 * (1.f/64.f);
    float rs = rsqrtf(s2*(1.f/64.f) - mean*mean + 1e-5f);
#pragma unroll
    for (int i = 0; i < 8; i++) {
        int c = fg*8 + i;
        d_xn2[(tok0 + t)*64 + c] = (vals[i] - mean) * rs * n2g[c] + n2b[c];
    }
}

// depthwise 3x3 + 5x5 (mult 4): thread = (channel, mult), weights in registers
__global__ __launch_bounds__(128) void k5b_dw(const float* __restrict__ w3,
                                              const float* __restrict__ b3,
                                              const float* __restrict__ w5,
                                              const float* __restrict__ b5)
{
    __shared__ float patch[32*145];
    int tid = threadIdx.x;
    int tx = blockIdx.x, ty = blockIdx.y;
    int bz = blockIdx.z;
    int b = bz >> 1, half = bz & 1;
    for (int idx = tid; idx < 4608; idx += 128) {
        int c = idx / 144, pos = idx % 144;
        int py = pos / 12, px = pos % 12;
        int gy = ty*8 + py - 2, gx = tx*8 + px - 2;
        float v = 0.f;
        if (gy >= 0 && gy < 56 && gx >= 0 && gx < 56)
            v = d_xn2[(b*NN + gy*56 + gx)*64 + half*32 + c];
        patch[c*145 + pos] = v;
    }
    __syncthreads();
    int e = tid & 3, c = tid >> 2;
    int o = (half*32 + c)*4 + e;
    float w3r[9], w5r[25];
#pragma unroll
    for (int i = 0; i < 9; i++)  w3r[i] = w3[o*9 + i];
#pragma unroll
    for (int i = 0; i < 25; i++) w5r[i] = w5[o*25 + i];
    float b3r = b3[o], b5r = b5[o];
    const float* pr = &patch[c*145];
    int tokbase = b*NN + ty*8*56 + tx*8;
    for (int p = 0; p < 64; p++) {
        int py = p >> 3, px = p & 7;
        float n[25];
#pragma unroll
        for (int ky = 0; ky < 5; ky++)
#pragma unroll
        for (int kx = 0; kx < 5; kx++)
            n[ky*5+kx] = pr[(py + ky)*12 + px + kx];
        float a3 = b3r;
#pragma unroll
        for (int ky = 0; ky < 3; ky++)
#pragma unroll
        for (int kx = 0; kx < 3; kx++)
            a3 = fmaf(n[(ky+1)*5 + kx+1], w3r[ky*3+kx], a3);
        float a5 = b5r;
#pragma unroll
        for (int i = 0; i < 25; i++) a5 = fmaf(n[i], w5r[i], a5);
        int tok = tokbase + py*56 + px;
        d_cat[tok*512 + o]       = a3;
        d_cat[tok*512 + 256 + o] = a5;
    }
}

// 1x1 mix (512->64) + residual, weights tiled through smem, 2 tokens/thread
__global__ __launch_bounds__(128) void k5c_mix(const float* __restrict__ b1,
                                               float* __restrict__ out)
{
    __shared__ float cs[16*512];
    __shared__ float wsm[64*64];
    int tid = threadIdx.x;
    int tok0 = blockIdx.x * 16;
    for (int idx = tid; idx < 8192; idx += 128)
        cs[idx] = d_cat[tok0*512 + idx];
    int fg = tid & 15, ts = tid >> 4;
    int o0 = fg * 4;
    u64 a00 = pk(b1[o0], b1[o0+1]);
    u64 a01 = pk(b1[o0+2], b1[o0+3]);
    u64 a10 = a00, a11 = a01;
    for (int kt = 0; kt < 8; kt++) {
        __syncthreads();
        for (int idx = tid; idx < 4096; idx += 128)
            wsm[idx] = d_w1t[kt*4096 + idx];
        __syncthreads();
        const float* cA = &cs[ts*512 + kt*64];
        const float* cB = &cs[(ts+8)*512 + kt*64];
#pragma unroll 8
        for (int k = 0; k < 64; k++) {
            ulonglong2 w = *(const ulonglong2*)&wsm[k*64 + o0];
            u64 ca = pk2(cA[k]);
            u64 cb = pk2(cB[k]);
            a00 = ffma2(ca, w.x, a00); a01 = ffma2(ca, w.y, a01);
            a10 = ffma2(cb, w.x, a10); a11 = ffma2(cb, w.y, a11);
        }
    }
    float r0, r1, r2, r3;
    int tokA = tok0 + ts, tokB = tok0 + ts + 8;
    upk(a00, r0, r1); upk(a01, r2, r3);
    {
        float4 xv = *(const float4*)&d_x1[tokA*64 + o0];
        float4 ov; ov.x = xv.x + r0; ov.y = xv.y + r1; ov.z = xv.z + r2; ov.w = xv.w + r3;
        *(float4*)&out[tokA*64 + o0] = ov;
    }
    upk(a10, r0, r1); upk(a11, r2, r3);
    {
        float4 xv = *(const float4*)&d_x1[tokB*64 + o0];
        float4 ov; ov.x = xv.x + r0; ov.y = xv.y + r1; ov.z = xv.z + r2; ov.w = xv.w + r3;
        *(float4*)&out[tokB*64 + o0] = ov;
    }
}

extern "C" void kernel_launch(void* const* d_in, const int* in_sizes, int n_in,
                              void* d_out, int out_size)
{
    const float* x      = (const float*)d_in[0];
    const float* n1g    = (const float*)d_in[1];
    const float* n1b    = (const float*)d_in[2];
    const float* wq     = (const float*)d_in[3];
    const float* bq     = (const float*)d_in[4];
    const float* wkv    = (const float*)d_in[5];
    const float* bkv    = (const float*)d_in[6];
    const float* wproj  = (const float*)d_in[7];
    const float* bproj  = (const float*)d_in[8];
    const float* lw     = (const float*)d_in[9];
    const float* lb     = (const float*)d_in[10];
    const float* n2g    = (const float*)d_in[11];
    const float* n2b    = (const float*)d_in[12];
    const float* w3     = (const float*)d_in[13];
    const float* b3     = (const float*)d_in[14];
    const float* w5     = (const float*)d_in[15];
    const float* b5     = (const float*)d_in[16];
    const float* w1     = (const float*)d_in[17];
    const float* b1     = (const float*)d_in[18];
    float* out = (float*)d_out;

    cudaFuncSetAttribute(k3a_score, cudaFuncAttributeMaxDynamicSharedMemorySize, K3A_SMEM);

    k0_prep<<<321, 256>>>(wq, bq, wkv, bkv, lw, w1);     // 1
    k1_lnqkv<<<392, 256>>>(x, n1g, n1b);                 // 2
    k2a_sumv<<<dim3(4, 8), 256>>>();                     // 3
    k3a_score<<<dim3(49, KSPLIT, NB), 128, K3A_SMEM>>>();// 4  <- profiled slot
    k2b_sumv<<<4, 256>>>();                              // 5
    k3m_merge<<<196, 128>>>();                           // 6
    k3b_out<<<dim3(196, 4), 128>>>();                    // 7
    k4_convproj<<<dim3(7, 7, 4), 256>>>(x, n1g, n1b, wproj, bproj, lb); // 8
    k5a_ln2<<<392, 256>>>(n2g, n2b);                     // 9
    k5b_dw<<<dim3(7, 7, 8), 128>>>(w3, b3, w5, b5);      // 10
    k5c_mix<<<784, 128>>>(b1, out);                      // 11
}

// round 16
// speedup vs baseline: 1.4445x; 1.0752x over previous
#include <cuda_runtime.h>
#include <cuda_bf16.h>

#define NB 4
#define NN 3136
#define NTOK (NB*NN)
typedef unsigned long long u64;

__device__ __nv_bfloat16 d_qh[NTOK*64];
__device__ __nv_bfloat16 d_kh[NTOK*64];
__device__ float d_v[NTOK*64];
__device__ float d_g[NTOK*64];
__device__ float d_x1[NTOK*64];
__device__ float d_xn2[NTOK*64];
__device__ float d_cat[NTOK*512];
__device__ float d_sumv[NB*64];
__device__ float d_svp[NB*32*64];
__device__ float d_Wc[64*192];
__device__ float d_Wb[192];
__device__ float d_lwT[576*64];
__device__ float d_w1t[512*64];
__device__ float d_wd[NTOK*8];
__device__ int   d_wi[NTOK*8];
__device__ float d_bs[NTOK];
__device__ float d_cv[NTOK*56];
__device__ int   d_ci[NTOK*56];

__device__ __forceinline__ u64 ffma2(u64 a, u64 b, u64 c) {
    u64 d; asm("fma.rn.f32x2 %0, %1, %2, %3;" : "=l"(d) : "l"(a), "l"(b), "l"(c)); return d;
}
__device__ __forceinline__ u64 fmul2(u64 a, u64 b) {
    u64 d; asm("mul.rn.f32x2 %0, %1, %2;" : "=l"(d) : "l"(a), "l"(b)); return d;
}
__device__ __forceinline__ u64 pk2(float v) {
    u64 d; asm("mov.b64 %0, {%1, %1};" : "=l"(d) : "f"(v)); return d;
}
__device__ __forceinline__ u64 pk(float lo, float hi) {
    u64 d; asm("mov.b64 %0, {%1, %2};" : "=l"(d) : "f"(lo), "f"(hi)); return d;
}
__device__ __forceinline__ void upk(u64 v, float& lo, float& hi) {
    asm("mov.b64 {%0, %1}, %2;" : "=f"(lo), "=f"(hi) : "l"(v));
}

__global__ void k0_prep(const float* __restrict__ wq, const float* __restrict__ bq,
                        const float* __restrict__ wkv, const float* __restrict__ bkv,
                        const float* __restrict__ lw, const float* __restrict__ w1)
{
    int i = blockIdx.x * 256 + threadIdx.x;
    if (i < 64*192) {
        int k = i / 192, f = i % 192;
        d_Wc[i] = (f < 64) ? wq[k*64 + f] : wkv[k*128 + (f - 64)];
    }
    int j = i - 64*192;
    if (j >= 0 && j < 192) d_Wb[j] = (j < 64) ? bq[j] : bkv[j - 64];
    int l = i - (64*192 + 192);
    if (l >= 0 && l < 576*64) d_lwT[l] = lw[(l % 64)*576 + (l / 64)];
    int m = i - (64*192 + 192 + 576*64);
    if (m >= 0 && m < 512*64) d_w1t[m] = w1[(m % 64)*512 + (m / 64)];
}

// LN1 + fused QKV projection: q,k emitted as bf16; v as fp32
__global__ __launch_bounds__(256) void k1_lnqkv(const float* __restrict__ x,
                                                const float* __restrict__ n1g,
                                                const float* __restrict__ n1b)
{
    __shared__ float xs[32*65];
    int tid = threadIdx.x;
    int tok0 = blockIdx.x * 32;
    for (int idx = tid; idx < 2048; idx += 256) {
        int t = idx >> 6, c = idx & 63;
        xs[t*65 + c] = x[(tok0 + t)*64 + c];
    }
    __syncthreads();
    int t = tid >> 3, fg = tid & 7;
    float vals[8], s1 = 0.f, s2 = 0.f;
#pragma unroll
    for (int i = 0; i < 8; i++) {
        float v = xs[t*65 + fg*8 + i];
        vals[i] = v; s1 += v; s2 += v*v;
    }
#pragma unroll
    for (int o = 1; o < 8; o <<= 1) {
        s1 += __shfl_xor_sync(0xffffffffu, s1, o);
        s2 += __shfl_xor_sync(0xffffffffu, s2, o);
    }
    float mean = s1 * (1.f/64.f);
    float rs = rsqrtf(s2*(1.f/64.f) - mean*mean + 1e-5f);
#pragma unroll
    for (int i = 0; i < 8; i++) {
        int c = fg*8 + i;
        xs[t*65 + c] = (vals[i] - mean) * rs * n1g[c] + n1b[c];
    }
    __syncthreads();
    int f0 = fg * 24;
    u64 acc[12];
#pragma unroll
    for (int j = 0; j < 12; j++) acc[j] = pk(d_Wb[f0 + 2*j], d_Wb[f0 + 2*j + 1]);
#pragma unroll 4
    for (int k = 0; k < 64; k++) {
        u64 xv2 = pk2(xs[t*65 + k]);
        const ulonglong2* wr = (const ulonglong2*)&d_Wc[k*192 + f0];
#pragma unroll
        for (int j2 = 0; j2 < 6; j2++) {
            ulonglong2 w = wr[j2];
            acc[j2*2+0] = ffma2(xv2, w.x, acc[j2*2+0]);
            acc[j2*2+1] = ffma2(xv2, w.y, acc[j2*2+1]);
        }
    }
    int tok = tok0 + t;
#pragma unroll
    for (int j = 0; j < 12; j++) {
        float lo, hi; upk(acc[j], lo, hi);
        int f = f0 + 2*j;
#pragma unroll
        for (int e = 0; e < 2; e++) {
            int ff = f + e;
            float v = e ? hi : lo;
            if (ff < 64)       d_qh[tok*64 + ff] = __float2bfloat16(v);
            else if (ff < 128) d_kh[tok*64 + ff - 64] = __float2bfloat16(v);
            else               d_v[tok*64 + ff - 128] = v;
        }
    }
}

__global__ void k2a_sumv()
{
    int b = blockIdx.x, oct = blockIdx.y;
    int c = threadIdx.x & 63, sg = threadIdx.x >> 6;
    float a = 0.f;
    int base = b*NN + oct*392 + sg*98;
#pragma unroll 4
    for (int j = 0; j < 98; j++) a += d_v[(base + j)*64 + c];
    d_svp[(b*32 + oct*4 + sg)*64 + c] = a;
}
__global__ void k2b_sumv()
{
    __shared__ float red[4][64];
    int b = blockIdx.x;
    int c = threadIdx.x & 63, part = threadIdx.x >> 6;
    float a = 0.f;
#pragma unroll
    for (int s = 0; s < 8; s++) a += d_svp[(b*32 + part*8 + s)*64 + c];
    red[part][c] = a;
    __syncthreads();
    if (part == 0)
        d_sumv[b*64 + c] = (red[0][c] + red[1][c]) + (red[2][c] + red[3][c]);
}

#define SWP(a,b,ia,ib) if (a > b) { float tf_=a; a=b; b=tf_; int ti_=ia; ia=ib; ib=ti_; }
#define KSPLIT 7
#define TPS 448
#define K3A_SMEM 44544

// Tensor-core scorer: 64 queries x 448 keys per block (7 tiles of 64).
__global__ __launch_bounds__(128, 4) void k3a_score()
{
    extern __shared__ __align__(16) char smem[];
    __nv_bfloat16* qh = (__nv_bfloat16*)smem;           // 64 x 72
    __nv_bfloat16* kt = (__nv_bfloat16*)(smem + 9216);  // 2 x (64 x 72)
    float* ss = (float*)(smem + 27648);                 // 64 x 66
    int tid = threadIdx.x;
    int lane = tid & 31, w = tid >> 5;
    int b = blockIdx.z, split = blockIdx.y;
    int q0 = blockIdx.x * 64;
    int kbase = split * TPS;

#pragma unroll
    for (int i = 0; i < 4; i++) {
        int fi = i*128 + tid;
        int row = fi >> 3, ch = fi & 7;
        *(float4*)&qh[row*72 + ch*8] =
            *(const float4*)&d_qh[(b*NN + q0 + row)*64 + ch*8];
    }
    {
        const __nv_bfloat16* src0 = &d_kh[(b*NN + kbase)*64];
#pragma unroll
        for (int i = 0; i < 4; i++) {
            int fi = i*128 + tid;
            int row = fi >> 3, ch = fi & 7;
            unsigned int dst = (unsigned int)__cvta_generic_to_shared(&kt[row*72 + ch*8]);
            asm volatile("cp.async.cg.shared.global [%0], [%1], 16;"
                         :: "r"(dst), "l"(src0 + row*64 + ch*8));
        }
        asm volatile("cp.async.commit_group;");
    }

    int qw = w * 16;
    unsigned int a_base = (unsigned int)__cvta_generic_to_shared(
        &qh[(qw + (lane & 15))*72 + (lane >> 4)*8]);
    int lane16 = lane & 15;
    unsigned int b_off = (unsigned int)((lane16 & 7)*72 + (lane16 >> 3)*8) * 2;

    int sq = tid >> 1, sp = tid & 1;
    float t0=-1e30f,t1=-1e30f,t2=-1e30f,t3=-1e30f,t4=-1e30f,t5=-1e30f,t6=-1e30f,t7=-1e30f;
    int   i0=0,i1=0,i2=0,i3=0,i4=0,i5=0,i6=0,i7=0;

    for (int t = 0; t < 7; t++) {
        if (t < 6) {
            const __nv_bfloat16* srcn = &d_kh[(b*NN + kbase + (t+1)*64)*64];
            __nv_bfloat16* dstb = &kt[((t+1)&1)*4608];
#pragma unroll
            for (int i = 0; i < 4; i++) {
                int fi = i*128 + tid;
                int row = fi >> 3, ch = fi & 7;
                unsigned int dst = (unsigned int)__cvta_generic_to_shared(&dstb[row*72 + ch*8]);
                asm volatile("cp.async.cg.shared.global [%0], [%1], 16;"
                             :: "r"(dst), "l"(srcn + row*64 + ch*8));
            }
            asm volatile("cp.async.commit_group;");
            asm volatile("cp.async.wait_group 1;");
        } else {
            asm volatile("cp.async.wait_group 0;");
        }
        __syncthreads();

        unsigned int kta = (unsigned int)__cvta_generic_to_shared(&kt[(t&1)*4608]);
        float acc[8][4];
#pragma unroll
        for (int n = 0; n < 8; n++)
#pragma unroll
            for (int e = 0; e < 4; e++) acc[n][e] = 0.f;

#pragma unroll
        for (int s = 0; s < 4; s++) {
            unsigned int ra0, ra1, ra2, ra3;
            asm volatile("ldmatrix.sync.aligned.m8n8.x4.shared.b16 {%0,%1,%2,%3}, [%4];"
                         : "=r"(ra0), "=r"(ra1), "=r"(ra2), "=r"(ra3)
                         : "r"(a_base + s*32));
#pragma unroll
            for (int n = 0; n < 8; n++) {
                unsigned int rb0, rb1;
                asm volatile("ldmatrix.sync.aligned.m8n8.x2.shared.b16 {%0,%1}, [%2];"
                             : "=r"(rb0), "=r"(rb1)
                             : "r"(kta + b_off + (unsigned int)(n*1152 + s*32)));
                asm volatile("mma.sync.aligned.m16n8k16.row.col.f32.bf16.bf16.f32 "
                             "{%0,%1,%2,%3}, {%4,%5,%6,%7}, {%8,%9}, {%0,%1,%2,%3};"
                             : "+f"(acc[n][0]), "+f"(acc[n][1]),
                               "+f"(acc[n][2]), "+f"(acc[n][3])
                             : "r"(ra0), "r"(ra1), "r"(ra2), "r"(ra3),
                               "r"(rb0), "r"(rb1));
            }
        }
        {
            int g = lane >> 2, col = (lane & 3)*2;
#pragma unroll
            for (int n = 0; n < 8; n++) {
                *(float2*)&ss[(qw+g)*66 + n*8 + col] =
                    make_float2(acc[n][0]*0.125f, acc[n][1]*0.125f);
                *(float2*)&ss[(qw+g+8)*66 + n*8 + col] =
                    make_float2(acc[n][2]*0.125f, acc[n][3]*0.125f);
            }
        }
        __syncthreads();
        {
            const float* sr = &ss[sq*66 + sp];
            int jb = kbase + t*64 + sp;
#pragma unroll
            for (int g8 = 0; g8 < 4; g8++) {
                float m8 = sr[2*(g8*8)];
#pragma unroll
                for (int e = 1; e < 8; e++) m8 = fmaxf(m8, sr[2*(g8*8 + e)]);
                if (m8 > t0) {
#pragma unroll
                    for (int e = 0; e < 8; e++) {
                        float v = sr[2*(g8*8 + e)];
                        if (v > t0) {
                            t0 = v; i0 = jb + 2*(g8*8 + e);
                            SWP(t0,t1,i0,i1) SWP(t1,t2,i1,i2) SWP(t2,t3,i2,i3) SWP(t3,t4,i3,i4)
                            SWP(t4,t5,i4,i5) SWP(t5,t6,i5,i6) SWP(t6,t7,i6,i7)
                        }
                    }
                }
            }
        }
    }
    __syncthreads();

    float* mvv = ss;
    int*   mii = (int*)(ss + 1024);
    int b8 = tid*8;
    mvv[b8+0]=t0; mvv[b8+1]=t1; mvv[b8+2]=t2; mvv[b8+3]=t3;
    mvv[b8+4]=t4; mvv[b8+5]=t5; mvv[b8+6]=t6; mvv[b8+7]=t7;
    mii[b8+0]=i0; mii[b8+1]=i1; mii[b8+2]=i2; mii[b8+3]=i3;
    mii[b8+4]=i4; mii[b8+5]=i5; mii[b8+6]=i6; mii[b8+7]=i7;
    __syncthreads();
    if (tid < 64) {
        int q = tid;
        int base = q*16;
        int qtok = b*NN + q0 + q;
#pragma unroll
        for (int pass = 0; pass < 8; pass++) {
            float best = -1e30f; int bp = base;
#pragma unroll
            for (int e = 0; e < 16; e++) {
                float v = mvv[base + e];
                if (v > best) { best = v; bp = base + e; }
            }
            d_cv[qtok*56 + split*8 + pass] = best;
            d_ci[qtok*56 + split*8 + pass] = mii[bp];
            mvv[bp] = -1e30f;
        }
    }
}

// merge 7 split candidate lists per query -> global top-8 + softmax weights
__global__ __launch_bounds__(128) void k3m_merge()
{
    __shared__ float cv[64*57];
    __shared__ int   ci[64*57];
    int tid = threadIdx.x;
    int q0 = blockIdx.x * 64;
    for (int idx = tid; idx < 64*56; idx += 128) {
        int q = idx / 56, e = idx % 56;
        cv[q*57 + e] = d_cv[(q0 + q)*56 + e];
        ci[q*57 + e] = d_ci[(q0 + q)*56 + e];
    }
    __syncthreads();
    if (tid < 64) {
        int q = tid;
        int qtok = q0 + q;
        float tv[8]; int ti[8];
#pragma unroll
        for (int pass = 0; pass < 8; pass++) {
            float best = -1e30f; int bp = 0;
            for (int e = 0; e < 56; e++) {
                float v = cv[q*57 + e];
                if (v > best) { best = v; bp = e; }
            }
            tv[pass] = best; ti[pass] = ci[q*57 + bp]; cv[q*57 + bp] = -1e30f;
        }
        float m = fmaxf(tv[0], 0.f);
        float ex[8], se = 0.f;
#pragma unroll
        for (int t = 0; t < 8; t++) { ex[t] = __expf(tv[t] - m); se += ex[t]; }
        float em = __expf(-m);
        float invZ = 1.f / ((float)(NN - 8) * em + se);
        float bsv = em * invZ;
        d_bs[qtok] = bsv;
#pragma unroll
        for (int t = 0; t < 8; t++) {
            d_wd[qtok*8 + t] = ex[t]*invZ - bsv;
            d_wi[qtok*8 + t] = ti[t];
        }
    }
}

// gather output: g = bs*sum_v + sum_t wd_t * v[wi_t]
__global__ __launch_bounds__(128) void k3b_out()
{
    int tid = threadIdx.x;
    int b = blockIdx.y;
    int rr = tid >> 3;
    int c0 = (tid & 7) << 3;
    int tok = b*NN + blockIdx.x*16 + rr;
    float bsv = d_bs[tok];
    u64 bsv2 = pk2(bsv);
    u64 acc[4];
    const ulonglong2* sv = (const ulonglong2*)&d_sumv[b*64 + c0];
    {
        ulonglong2 s0 = sv[0], s1 = sv[1];
        acc[0] = fmul2(bsv2, s0.x); acc[1] = fmul2(bsv2, s0.y);
        acc[2] = fmul2(bsv2, s1.x); acc[3] = fmul2(bsv2, s1.y);
    }
#pragma unroll
    for (int t = 0; t < 8; t++) {
        u64 w2 = pk2(d_wd[tok*8 + t]);
        int jj = d_wi[tok*8 + t];
        const ulonglong2* vp = (const ulonglong2*)&d_v[(b*NN + jj)*64 + c0];
        ulonglong2 v0 = vp[0], v1 = vp[1];
        acc[0] = ffma2(w2, v0.x, acc[0]); acc[1] = ffma2(w2, v0.y, acc[1]);
        acc[2] = ffma2(w2, v1.x, acc[2]); acc[3] = ffma2(w2, v1.y, acc[3]);
    }
    u64* go = (u64*)&d_g[tok*64 + c0];
#pragma unroll
    for (int j = 0; j < 4; j++) go[j] = acc[j];
}

// dense 3x3 conv + proj(g) + LN + residual, half-tile (4x8 positions) per block
__global__ __launch_bounds__(256) void k4_convproj(const float* __restrict__ x,
                                                   const float* __restrict__ n1g,
                                                   const float* __restrict__ n1b,
                                                   const float* __restrict__ wproj,
                                                   const float* __restrict__ bproj,
                                                   const float* __restrict__ localb)
{
    __shared__ float patch[64*61];   // 64 ch x (6 rows x 10 cols), 15.6KB
    __shared__ float wsm[2304];      // 9.2KB
    int tid = threadIdx.x;
    int tx = blockIdx.x, ty = blockIdx.y;
    int bz = blockIdx.z;
    int b = bz >> 1, ph = bz & 1;
    for (int idx = tid; idx < 3840; idx += 256) {
        int c = idx & 63, pos = idx >> 6;       // pos 0..59
        int lpy = pos / 10, px = pos % 10;
        int gy = ty*8 + ph*4 + lpy - 1, gx = tx*8 + px - 1;
        float v = 0.f;
        if (gy >= 0 && gy < 56 && gx >= 0 && gx < 56)
            v = x[(b*NN + gy*56 + gx)*64 + c];
        patch[c*61 + pos] = v;
    }
    int p = tid >> 3;                // 0..31
    int c0 = (tid & 7) << 3;         // 8 channels
    int py = p >> 3, px = p & 7;     // py 0..3
    u64 acc[4];
#pragma unroll
    for (int j = 0; j < 4; j++)
        acc[j] = pk(localb[c0+2*j] + bproj[c0+2*j], localb[c0+2*j+1] + bproj[c0+2*j+1]);

    for (int ch = 0; ch < 16; ch++) {
        __syncthreads();
        for (int idx = tid; idx < 2304; idx += 256)
            wsm[idx] = d_lwT[ch*2304 + idx];
        __syncthreads();
#pragma unroll
        for (int cil = 0; cil < 4; cil++) {
            const float* prow = &patch[(ch*4 + cil)*61];
#pragma unroll
            for (int ky = 0; ky < 3; ky++)
#pragma unroll
            for (int kx = 0; kx < 3; kx++) {
                u64 pv2 = pk2(prow[(py + ky)*10 + px + kx]);
                const ulonglong2* wr = (const ulonglong2*)&wsm[(cil*9 + ky*3 + kx)*64 + c0];
                ulonglong2 wa = wr[0], wb = wr[1];
                acc[0] = ffma2(pv2, wa.x, acc[0]); acc[1] = ffma2(pv2, wa.y, acc[1]);
                acc[2] = ffma2(pv2, wb.x, acc[2]); acc[3] = ffma2(pv2, wb.y, acc[3]);
            }
        }
    }
    int tokk = b*NN + (ty*8 + ph*4 + py)*56 + tx*8 + px;
    for (int kc = 0; kc < 4; kc++) {
        __syncthreads();
        for (int idx = tid; idx < 1024; idx += 256)
            wsm[idx] = wproj[kc*1024 + idx];
        __syncthreads();
        float4 g4[4];
        const float4* gp = (const float4*)&d_g[tokk*64 + kc*16];
#pragma unroll
        for (int j = 0; j < 4; j++) g4[j] = gp[j];
#pragma unroll
        for (int k = 0; k < 16; k++) {
            float gv = ((const float*)g4)[k];
            u64 gv2 = pk2(gv);
            const ulonglong2* wr = (const ulonglong2*)&wsm[k*64 + c0];
            ulonglong2 wa = wr[0], wb = wr[1];
            acc[0] = ffma2(gv2, wa.x, acc[0]); acc[1] = ffma2(gv2, wa.y, acc[1]);
            acc[2] = ffma2(gv2, wb.x, acc[2]); acc[3] = ffma2(gv2, wb.y, acc[3]);
        }
    }
    float va[8];
#pragma unroll
    for (int j = 0; j < 4; j++) upk(acc[j], va[2*j], va[2*j+1]);
    float s1 = 0.f, s2 = 0.f;
#pragma unroll
    for (int j = 0; j < 8; j++) { s1 += va[j]; s2 += va[j]*va[j]; }
    s1 += __shfl_xor_sync(0xffffffffu, s1, 1);
    s2 += __shfl_xor_sync(0xffffffffu, s2, 1);
    s1 += __shfl_xor_sync(0xffffffffu, s1, 2);
    s2 += __shfl_xor_sync(0xffffffffu, s2, 2);
    s1 += __shfl_xor_sync(0xffffffffu, s1, 4);
    s2 += __shfl_xor_sync(0xffffffffu, s2, 4);
    float mean = s1 * (1.f/64.f);
    float rs = rsqrtf(s2*(1.f/64.f) - mean*mean + 1e-5f);
#pragma unroll
    for (int j = 0; j < 8; j++) {
        int c = c0 + j;
        float xv = patch[c*61 + (py + 1)*10 + px + 1];
        d_x1[tokk*64 + c] = xv + (va[j] - mean) * rs * n1g[c] + n1b[c];
    }
}

__global__ __launch_bounds__(256) void k5a_ln2(const float* __restrict__ n2g,
                                               const float* __restrict__ n2b)
{
    __shared__ float xs[32*65];
    int tid = threadIdx.x;
    int tok0 = blockIdx.x * 32;
    for (int idx = tid; idx < 2048; idx += 256) {
        int t = idx >> 6, c = idx & 63;
        xs[t*65 + c] = d_x1[(tok0 + t)*64 + c];
    }
    __syncthreads();
    int t = tid >> 3, fg = tid & 7;
    float vals[8], s1 = 0.f, s2 = 0.f;
#pragma unroll
    for (int i = 0; i < 8; i++) {
        float v = xs[t*65 + fg*8 + i];
        vals[i] = v; s1 += v; s2 += v*v;
    }
#pragma unroll
    for (int o = 1; o < 8; o <<= 1) {
        s1 += __shfl_xor_sync(0xffffffffu, s1, o);
        s2 += __shfl_xor_sync(0xffffffffu, s2, o);
    }
    float mean = s1 * (1.f/64.f);
    float rs = rsqrtf(s2*(1.f/64.f) - mean*mean + 1e-5f);
#pragma unroll
    for (int i = 0; i < 8; i++) {
        int c = fg*8 + i;
        d_xn2[(tok0 + t)*64 + c] = (vals[i] - mean) * rs * n2g[c] + n2b[c];
    }
}

// depthwise 3x3 + 5x5 (mult 4): half-tile (4x8 positions), 32 ch per block
__global__ __launch_bounds__(128) void k5b_dw(const float* __restrict__ w3,
                                              const float* __restrict__ b3,
                                              const float* __restrict__ w5,
                                              const float* __restrict__ b5)
{
    __shared__ float patch[32*97];   // 32 ch x (8 rows x 12 cols), 12.4KB
    int tid = threadIdx.x;
    int tx = blockIdx.x, ty = blockIdx.y;
    int bz = blockIdx.z;
    int b = bz >> 2, half = (bz >> 1) & 1, ph = bz & 1;
    for (int idx = tid; idx < 3072; idx += 128) {
        int c = idx / 96, pos = idx % 96;
        int lpy = pos / 12, px = pos % 12;
        int gy = ty*8 + ph*4 + lpy - 2, gx = tx*8 + px - 2;
        float v = 0.f;
        if (gy >= 0 && gy < 56 && gx >= 0 && gx < 56)
            v = d_xn2[(b*NN + gy*56 + gx)*64 + half*32 + c];
        patch[c*97 + pos] = v;
    }
    __syncthreads();
    int e = tid & 3, c = tid >> 2;
    int o = (half*32 + c)*4 + e;
    float w3r[9], w5r[25];
#pragma unroll
    for (int i = 0; i < 9; i++)  w3r[i] = w3[o*9 + i];
#pragma unroll
    for (int i = 0; i < 25; i++) w5r[i] = w5[o*25 + i];
    float b3r = b3[o], b5r = b5[o];
    const float* pr = &patch[c*97];
    int tokbase = b*NN + (ty*8 + ph*4)*56 + tx*8;
    for (int p = 0; p < 32; p++) {
        int py = p >> 3, px = p & 7;
        float n[25];
#pragma unroll
        for (int ky = 0; ky < 5; ky++)
#pragma unroll
        for (int kx = 0; kx < 5; kx++)
            n[ky*5+kx] = pr[(py + ky)*12 + px + kx];
        float a3 = b3r;
#pragma unroll
        for (int ky = 0; ky < 3; ky++)
#pragma unroll
        for (int kx = 0; kx < 3; kx++)
            a3 = fmaf(n[(ky+1)*5 + kx+1], w3r[ky*3+kx], a3);
        float a5 = b5r;
#pragma unroll
        for (int i = 0; i < 25; i++) a5 = fmaf(n[i], w5r[i], a5);
        int tok = tokbase + py*56 + px;
        d_cat[tok*512 + o]       = a3;
        d_cat[tok*512 + 256 + o] = a5;
    }
}

// 1x1 mix (512->64) + residual, 256 threads, 1 token/thread
__global__ __launch_bounds__(256) void k5c_mix(const float* __restrict__ b1,
                                               float* __restrict__ out)
{
    __shared__ float cs[16*512];
    __shared__ float wsm[64*64];
    int tid = threadIdx.x;
    int tok0 = blockIdx.x * 16;
    for (int idx = tid; idx < 8192; idx += 256)
        cs[idx] = d_cat[tok0*512 + idx];
    int fg = tid & 15, ts = tid >> 4;
    int o0 = fg * 4;
    u64 a00 = pk(b1[o0], b1[o0+1]);
    u64 a01 = pk(b1[o0+2], b1[o0+3]);
    for (int kt = 0; kt < 8; kt++) {
        __syncthreads();
        for (int idx = tid; idx < 4096; idx += 256)
            wsm[idx] = d_w1t[kt*4096 + idx];
        __syncthreads();
        const float* cA = &cs[ts*512 + kt*64];
#pragma unroll 8
        for (int k = 0; k < 64; k++) {
            ulonglong2 w = *(const ulonglong2*)&wsm[k*64 + o0];
            u64 ca = pk2(cA[k]);
            a00 = ffma2(ca, w.x, a00); a01 = ffma2(ca, w.y, a01);
        }
    }
    float r0, r1, r2, r3;
    int tok = tok0 + ts;
    upk(a00, r0, r1); upk(a01, r2, r3);
    float4 xv = *(const float4*)&d_x1[tok*64 + o0];
    float4 ov; ov.x = xv.x + r0; ov.y = xv.y + r1; ov.z = xv.z + r2; ov.w = xv.w + r3;
    *(float4*)&out[tok*64 + o0] = ov;
}

extern "C" void kernel_launch(void* const* d_in, const int* in_sizes, int n_in,
                              void* d_out, int out_size)
{
    const float* x      = (const float*)d_in[0];
    const float* n1g    = (const float*)d_in[1];
    const float* n1b    = (const float*)d_in[2];
    const float* wq     = (const float*)d_in[3];
    const float* bq     = (const float*)d_in[4];
    const float* wkv    = (const float*)d_in[5];
    const float* bkv    = (const float*)d_in[6];
    const float* wproj  = (const float*)d_in[7];
    const float* bproj  = (const float*)d_in[8];
    const float* lw     = (const float*)d_in[9];
    const float* lb     = (const float*)d_in[10];
    const float* n2g    = (const float*)d_in[11];
    const float* n2b    = (const float*)d_in[12];
    const float* w3     = (const float*)d_in[13];
    const float* b3     = (const float*)d_in[14];
    const float* w5     = (const float*)d_in[15];
    const float* b5     = (const float*)d_in[16];
    const float* w1     = (const float*)d_in[17];
    const float* b1     = (const float*)d_in[18];
    float* out = (float*)d_out;

    cudaFuncSetAttribute(k3a_score, cudaFuncAttributeMaxDynamicSharedMemorySize, K3A_SMEM);

    k0_prep<<<321, 256>>>(wq, bq, wkv, bkv, lw, w1);     // 1
    k1_lnqkv<<<392, 256>>>(x, n1g, n1b);                 // 2
    k2a_sumv<<<dim3(4, 8), 256>>>();                     // 3
    k3a_score<<<dim3(49, KSPLIT, NB), 128, K3A_SMEM>>>();// 4  <- profiled slot
    k2b_sumv<<<4, 256>>>();                              // 5
    k3m_merge<<<196, 128>>>();                           // 6
    k3b_out<<<dim3(196, 4), 128>>>();                    // 7
    k4_convproj<<<dim3(7, 7, 8), 256>>>(x, n1g, n1b, wproj, bproj, lb); // 8
    k5a_ln2<<<392, 256>>>(n2g, n2b);                     // 9
    k5b_dw<<<dim3(7, 7, 16), 128>>>(w3, b3, w5, b5);     // 10
    k5c_mix<<<784, 256>>>(b1, out);                      // 11
}